// round 16
// baseline (speedup 1.0000x reference)
#include <cuda_runtime.h>
#include <cuda_bf16.h>
#include <cstdint>

#define BB 8
#define CC 128
#define WW 4096
#define DD 16

// 0.25 (= D^-0.5) * log2(e): folded into q so softmax uses exp2 directly.
#define QSCALE 0.3606737602222409f

typedef unsigned long long ull;

// ---- scratch (__device__ globals; no allocs allowed) ----------------------
__device__ __nv_bfloat16 g_q[(size_t)BB*WW*DD];   // [b][w][d], pre-scaled
__device__ __nv_bfloat16 g_k[(size_t)BB*WW*DD];   // [b][w][d]
__device__ __nv_bfloat16 g_v[(size_t)BB*CC*WW];   // [b][c][w]; stats scales by 1/l
__device__ int g_ctr;                              // work-steal counter
__device__ int g_done[BB];                         // per-batch stats completion

// ---- helpers --------------------------------------------------------------
__device__ __forceinline__ uint32_t smem_u32(const void* p) {
    uint32_t a;
    asm("{ .reg .u64 t; cvta.to.shared.u64 t, %1; cvt.u32.u64 %0, t; }"
        : "=r"(a) : "l"(p));
    return a;
}
__device__ __forceinline__ uint32_t bf2u(__nv_bfloat162 h) {
    return *reinterpret_cast<uint32_t*>(&h);
}

// ---- mma.sync m16n8k16 bf16 (A row-major, B col-major, f32 accum) ---------
__device__ __forceinline__ void mma_acc(float* d, const uint32_t* a,
                                        uint32_t b0, uint32_t b1) {
    asm volatile("mma.sync.aligned.m16n8k16.row.col.f32.bf16.bf16.f32 "
        "{%0,%1,%2,%3}, {%4,%5,%6,%7}, {%8,%9}, {%0,%1,%2,%3};"
        : "+f"(d[0]), "+f"(d[1]), "+f"(d[2]), "+f"(d[3])
        : "r"(a[0]), "r"(a[1]), "r"(a[2]), "r"(a[3]), "r"(b0), "r"(b1));
}
__device__ __forceinline__ void mma_z(float* d, const uint32_t* a,
                                      uint32_t b0, uint32_t b1) {
    asm volatile("mma.sync.aligned.m16n8k16.row.col.f32.bf16.bf16.f32 "
        "{%0,%1,%2,%3}, {%4,%5,%6,%7}, {%8,%9}, {%10,%10,%10,%10};"
        : "=f"(d[0]), "=f"(d[1]), "=f"(d[2]), "=f"(d[3])
        : "r"(a[0]), "r"(a[1]), "r"(a[2]), "r"(a[3]), "r"(b0), "r"(b1),
          "f"(0.0f));
}
#define LDMX4(v0, v1, v2, v3, addr) \
    asm volatile("ldmatrix.sync.aligned.m8n8.x4.shared.b16 {%0,%1,%2,%3}, [%4];" \
        : "=r"(v0), "=r"(v1), "=r"(v2), "=r"(v3) : "r"(addr))

// ---- cp.async -------------------------------------------------------------
#define CP16(dst, src) asm volatile("cp.async.cg.shared.global [%0], [%1], 16;" :: "r"(dst), "l"(src))
#define CP8(dst, src)  asm volatile("cp.async.ca.shared.global [%0], [%1], 8;"  :: "r"(dst), "l"(src))
#define CP_COMMIT()    asm volatile("cp.async.commit_group;" ::: "memory")
#define CP_WAIT0()     asm volatile("cp.async.wait_group 0;" ::: "memory")
#define CP_WAIT1()     asm volatile("cp.async.wait_group 1;" ::: "memory")

// ===========================================================================
// Kernel 1: projections via bf16 HMMA (R9/R14 version — best measured).
// Zeroes work counter + per-batch done flags for this launch.
// ===========================================================================
#define SPX 272
#define OFX 0
#define OFW 34816
#define OFQ 69632
#define OFT 78336

__global__ void __launch_bounds__(256) k_proj(
    const float* __restrict__ x,
    const float* __restrict__ Wq, const float* __restrict__ bq,
    const float* __restrict__ Wk, const float* __restrict__ bk,
    const float* __restrict__ Wv, const float* __restrict__ bv)
{
    extern __shared__ __align__(16) char smc[];
    const int b   = blockIdx.y;
    const int w0  = blockIdx.x * 128;
    const int tid = threadIdx.x;
    const int wid = tid >> 5;
    const int lane = tid & 31;
    const int g = lane >> 2, t = lane & 3;

    if (blockIdx.x == 0 && blockIdx.y == 0 && tid < 9) {
        if (tid == 0) g_ctr = 0;
        else g_done[tid - 1] = 0;
    }

    for (int i = tid; i < 128*32; i += 256) {
        int r = i >> 5, cf = i & 31;
        float4 v = *(const float4*)(Wv + r*128 + cf*4);
        uint2 o;
        o.x = bf2u(__floats2bfloat162_rn(v.x, v.y));
        o.y = bf2u(__floats2bfloat162_rn(v.z, v.w));
        *(uint2*)(smc + OFW + r*SPX + cf*8) = o;
    }
    for (int i = tid; i < 32*32; i += 256) {
        int r = i >> 5, cf = i & 31;
        const float* src = (r < 16) ? (Wq + r*128 + cf*4) : (Wk + (r-16)*128 + cf*4);
        float4 v = *(const float4*)src;
        uint2 o;
        o.x = bf2u(__floats2bfloat162_rn(v.x, v.y));
        o.y = bf2u(__floats2bfloat162_rn(v.z, v.w));
        *(uint2*)(smc + OFQ + r*SPX + cf*8) = o;
    }
    {
        const int c = tid & 127, hf = tid >> 7;
        const float* xp = x + (size_t)(b*CC + c)*WW + w0 + hf*64;
        #pragma unroll
        for (int it = 0; it < 16; it++) {
            float4 v = *(const float4*)(xp + it*4);
            int w = hf*64 + it*4;
            *(__nv_bfloat16*)(smc + OFX + (w  )*SPX + c*2) = __float2bfloat16(v.x);
            *(__nv_bfloat16*)(smc + OFX + (w+1)*SPX + c*2) = __float2bfloat16(v.y);
            *(__nv_bfloat16*)(smc + OFX + (w+2)*SPX + c*2) = __float2bfloat16(v.z);
            *(__nv_bfloat16*)(smc + OFX + (w+3)*SPX + c*2) = __float2bfloat16(v.w);
        }
    }
    __syncthreads();

    {   // V GEMM
        const int mb = wid * 16;
        uint32_t A[8][4];
        #pragma unroll
        for (int kt = 0; kt < 8; kt++) {
            const char* r0 = smc + OFW + (mb + g)*SPX + kt*32 + t*4;
            const char* r1 = smc + OFW + (mb + g + 8)*SPX + kt*32 + t*4;
            A[kt][0] = *(const uint32_t*)r0;
            A[kt][1] = *(const uint32_t*)r1;
            A[kt][2] = *(const uint32_t*)(r0 + 16);
            A[kt][3] = *(const uint32_t*)(r1 + 16);
        }
        const float bias0 = bv[mb + g], bias1 = bv[mb + g + 8];
        #pragma unroll
        for (int nt = 0; nt < 16; nt++) {
            float acc[4] = {bias0, bias0, bias1, bias1};
            #pragma unroll
            for (int kt = 0; kt < 8; kt++) {
                const char* bp = smc + OFX + (nt*8 + g)*SPX + kt*32 + t*4;
                uint32_t b0 = *(const uint32_t*)bp;
                uint32_t b1 = *(const uint32_t*)(bp + 16);
                mma_acc(acc, A[kt], b0, b1);
            }
            const int wcol = w0 + nt*8 + 2*t;
            *(uint32_t*)(g_v + (size_t)(b*CC + mb + g)*WW + wcol) =
                bf2u(__floats2bfloat162_rn(acc[0], acc[1]));
            *(uint32_t*)(g_v + (size_t)(b*CC + mb + g + 8)*WW + wcol) =
                bf2u(__floats2bfloat162_rn(acc[2], acc[3]));
        }
    }

    {   // QK GEMM
        const int mt = wid & 1, ntb = (wid >> 1) * 4;
        uint32_t A[8][4];
        #pragma unroll
        for (int kt = 0; kt < 8; kt++) {
            const char* r0 = smc + OFQ + (mt*16 + g)*SPX + kt*32 + t*4;
            const char* r1 = smc + OFQ + (mt*16 + g + 8)*SPX + kt*32 + t*4;
            A[kt][0] = *(const uint32_t*)r0;
            A[kt][1] = *(const uint32_t*)r1;
            A[kt][2] = *(const uint32_t*)(r0 + 16);
            A[kt][3] = *(const uint32_t*)(r1 + 16);
        }
        const float* bias = mt ? bk : bq;
        const float bias0 = bias[g], bias1 = bias[g + 8];
        const float psc = mt ? 1.0f : QSCALE;
        #pragma unroll
        for (int nt = ntb; nt < ntb + 4; nt++) {
            float acc[4] = {bias0, bias0, bias1, bias1};
            #pragma unroll
            for (int kt = 0; kt < 8; kt++) {
                const char* bp = smc + OFX + (nt*8 + g)*SPX + kt*32 + t*4;
                uint32_t b0 = *(const uint32_t*)bp;
                uint32_t b1 = *(const uint32_t*)(bp + 16);
                mma_acc(acc, A[kt], b0, b1);
            }
            const int wcol = nt*8 + 2*t;
            *(uint32_t*)(smc + OFT + (mt*16 + g)*SPX + wcol*2) =
                bf2u(__floats2bfloat162_rn(acc[0]*psc, acc[1]*psc));
            *(uint32_t*)(smc + OFT + (mt*16 + g + 8)*SPX + wcol*2) =
                bf2u(__floats2bfloat162_rn(acc[2]*psc, acc[3]*psc));
        }
    }
    __syncthreads();

    {   // transpose qkT -> g_q/g_k [w][16]
        const int w = tid & 127, half = tid >> 7;
        uint32_t u[8];
        #pragma unroll
        for (int i = 0; i < 8; i++) {
            uint32_t lo = *(const uint16_t*)(smc + OFT + (half*16 + 2*i    )*SPX + w*2);
            uint32_t hi = *(const uint16_t*)(smc + OFT + (half*16 + 2*i + 1)*SPX + w*2);
            u[i] = lo | (hi << 16);
        }
        __nv_bfloat16* op = (half ? g_k : g_q) + (size_t)(b*WW + w0 + w)*DD;
        *(uint4*)op       = make_uint4(u[0], u[1], u[2], u[3]);
        *(uint4*)(op + 8) = make_uint4(u[4], u[5], u[6], u[7]);
    }
}

// ===========================================================================
// Kernel 2 (FUSED stats+ctx): persistent, 296 CTAs, 512 items.
// Schedule: stats b0,b1 -> blocks [ctx b_k | stats b_{k+2}] k=0..5 -> ctx b6,b7.
// ctx items spin (acquire) until their batch's 32 stats items completed.
// smem (dynamic 55296): stats uses QS@0(6144), KB@6144(12288),
// partial@18432(4096), red@22528(512), lpk@23040(256);
// ctx uses KS@0(6144), QR@6144(12288), VS@18432(36864); epi es@0(33792).
// ===========================================================================
#define SKD 48
#define SPJ 144
#define OF_KS 0
#define OF_QR 6144
#define OF_VS 18432

__global__ void __launch_bounds__(256, 2) k_main(const float* __restrict__ x,
                                                 float* __restrict__ out)
{
    extern __shared__ __align__(16) char smc[];
    __shared__ int s_item;
    const uint32_t smb = smem_u32(smc);
    const int tid = threadIdx.x;
    const int wid = tid >> 5;
    const int lane = tid & 31;
    const int g = lane >> 2, t = lane & 3;

    const uint32_t mlane_kd = (uint32_t)((((lane >> 4)*8 + (lane & 7))*SKD)
                                         + ((lane >> 3) & 1)*16);
    const uint32_t vlane = (uint32_t)((((lane >> 4)*8 + (lane & 7))*SPJ)
                                      + ((lane >> 3) & 1)*16);

    while (true) {
        if (tid == 0) s_item = atomicAdd(&g_ctr, 1);
        __syncthreads();
        const int p = s_item;
        __syncthreads();
        if (p >= 512) return;

        // ---- decode interleaved schedule ----
        int kind, b, tile;
        if (p < 64)        { kind = 0; b = p >> 5;            tile = p & 31; }
        else if (p < 448)  { int q = p - 64, k = q >> 6, r = q & 63;
                             if (r < 32) { kind = 1; b = k;     tile = r; }
                             else        { kind = 0; b = k + 2; tile = r - 32; } }
        else               { int r = p - 448; kind = 1; b = 6 + (r >> 5); tile = r & 31; }

        if (kind == 0) {
            // =============== STATS item: (b, j0 = tile*128) ===============
            const int j0 = tile << 7;
            char*  smq = smc;                    // q tile
            const uint32_t QS = smb;
            const uint32_t KB = smb + 6144;
            float (*partial)[128] = (float(*)[128])(smc + 18432);
            float* red = (float*)(smc + 22528);
            uint32_t* lpk = (uint32_t*)(smc + 23040);

            const uint32_t kw = KB + wid*(2*16*SKD);
            const uint32_t kldst = kw + (lane >> 1)*SKD + (lane & 1)*16;

            {
                int r = tid >> 1, h = tid & 1;
                CP16(QS + r*SKD + h*16,
                     (const char*)(g_q + (size_t)(b*WW + j0 + r)*DD) + h*16);
                CP16(kldst, (const char*)(g_k + (size_t)(b*WW + wid*16 + (lane >> 1))*DD)
                            + (lane & 1)*16);
            }
            CP_COMMIT(); CP_WAIT0();
            __syncthreads();

            uint32_t A[8][4];
            #pragma unroll
            for (int mt = 0; mt < 8; mt++) {
                const char* r0 = smq + (mt*16 + g)*SKD + t*4;
                const char* r1 = smq + (mt*16 + g + 8)*SKD + t*4;
                A[mt][0] = *(const uint32_t*)r0;
                A[mt][1] = *(const uint32_t*)r1;
                A[mt][2] = *(const uint32_t*)(r0 + 16);
                A[mt][3] = *(const uint32_t*)(r1 + 16);
            }

            float lacc[8][2];
            #pragma unroll
            for (int mt = 0; mt < 8; mt++) { lacc[mt][0] = 0.0f; lacc[mt][1] = 0.0f; }

            for (int it8 = 0; it8 < 4; it8++) {
                uint32_t acc01[8], acc23[8];
                #pragma unroll
                for (int mt = 0; mt < 8; mt++) { acc01[mt] = 0u; acc23[mt] = 0u; }
                #pragma unroll
                for (int i8 = 0; i8 < 8; i8++) {
                    const int it = it8*8 + i8;
                    if (it + 1 < 32) {
                        CP16(kldst + (uint32_t)(((it + 1) & 1)*(16*SKD)),
                             (const char*)(g_k + (size_t)(b*WW + (it + 1)*128 + wid*16
                                                          + (lane >> 1))*DD) + (lane & 1)*16);
                    }
                    CP_COMMIT();
                    CP_WAIT1();
                    uint32_t v0, v1, v2, v3;
                    LDMX4(v0, v1, v2, v3, kw + (uint32_t)((it & 1)*(16*SKD)) + mlane_kd);
                    #pragma unroll
                    for (int mt = 0; mt < 8; mt++) {
                        float d[4];
                        uint32_t h01, h23;
                        mma_z(d, A[mt], v0, v1);
                        asm("cvt.rn.f16x2.f32 %0, %1, %2;" : "=r"(h01) : "f"(d[1]), "f"(d[0]));
                        asm("cvt.rn.f16x2.f32 %0, %1, %2;" : "=r"(h23) : "f"(d[3]), "f"(d[2]));
                        asm("ex2.approx.f16x2 %0, %0;" : "+r"(h01));
                        asm("ex2.approx.f16x2 %0, %0;" : "+r"(h23));
                        asm("add.rn.f16x2 %0, %0, %1;" : "+r"(acc01[mt]) : "r"(h01));
                        asm("add.rn.f16x2 %0, %0, %1;" : "+r"(acc23[mt]) : "r"(h23));
                        mma_z(d, A[mt], v2, v3);
                        asm("cvt.rn.f16x2.f32 %0, %1, %2;" : "=r"(h01) : "f"(d[1]), "f"(d[0]));
                        asm("cvt.rn.f16x2.f32 %0, %1, %2;" : "=r"(h23) : "f"(d[3]), "f"(d[2]));
                        asm("ex2.approx.f16x2 %0, %0;" : "+r"(h01));
                        asm("ex2.approx.f16x2 %0, %0;" : "+r"(h23));
                        asm("add.rn.f16x2 %0, %0, %1;" : "+r"(acc01[mt]) : "r"(h01));
                        asm("add.rn.f16x2 %0, %0, %1;" : "+r"(acc23[mt]) : "r"(h23));
                    }
                }
                #pragma unroll
                for (int mt = 0; mt < 8; mt++) {
                    float f0, f1, f2, f3;
                    asm("{.reg .f16 lo, hi; mov.b32 {lo, hi}, %2; cvt.f32.f16 %0, lo; cvt.f32.f16 %1, hi;}"
                        : "=f"(f0), "=f"(f1) : "r"(acc01[mt]));
                    asm("{.reg .f16 lo, hi; mov.b32 {lo, hi}, %2; cvt.f32.f16 %0, lo; cvt.f32.f16 %1, hi;}"
                        : "=f"(f2), "=f"(f3) : "r"(acc23[mt]));
                    lacc[mt][0] += f0 + f1;
                    lacc[mt][1] += f2 + f3;
                }
            }

            #pragma unroll
            for (int mt = 0; mt < 8; mt++) {
                #pragma unroll
                for (int off = 1; off < 4; off <<= 1) {
                    lacc[mt][0] += __shfl_down_sync(0xffffffffu, lacc[mt][0], off, 4);
                    lacc[mt][1] += __shfl_down_sync(0xffffffffu, lacc[mt][1], off, 4);
                }
                if (t == 0) {
                    partial[wid][mt*16 + g]     = lacc[mt][0];
                    partial[wid][mt*16 + g + 8] = lacc[mt][1];
                }
            }
            __syncthreads();
            if (tid < 128) {
                float l = partial[0][tid] + partial[1][tid] + partial[2][tid] + partial[3][tid]
                        + partial[4][tid] + partial[5][tid] + partial[6][tid] + partial[7][tid];
                red[tid] = 1.0f / l;
            }
            __syncthreads();
            if (tid < 64)
                lpk[tid] = bf2u(__floats2bfloat162_rn(red[2*tid], red[2*tid + 1]));
            __syncthreads();

            {
                const int chunk = tid & 15;
                const int cb    = tid >> 4;
                uint32_t s0 = lpk[chunk*4], s1 = lpk[chunk*4 + 1];
                uint32_t s2 = lpk[chunk*4 + 2], s3 = lpk[chunk*4 + 3];
                #pragma unroll
                for (int c = cb; c < 128; c += 16) {
                    uint32_t* vp = (uint32_t*)(g_v + (size_t)(b*CC + c)*WW + j0 + chunk*8);
                    uint4 v = *(uint4*)vp;
                    asm("mul.rn.bf16x2 %0, %0, %1;" : "+r"(v.x) : "r"(s0));
                    asm("mul.rn.bf16x2 %0, %0, %1;" : "+r"(v.y) : "r"(s1));
                    asm("mul.rn.bf16x2 %0, %0, %1;" : "+r"(v.z) : "r"(s2));
                    asm("mul.rn.bf16x2 %0, %0, %1;" : "+r"(v.w) : "r"(s3));
                    *(uint4*)vp = v;
                }
            }
            __threadfence();          // publish g_v writes
            __syncthreads();
            if (tid == 0) atomicAdd(&g_done[b], 1);
            __syncthreads();          // smem safe for next item

        } else {
            // =============== CTX item: (b, w0 = tile*128) =================
            const int w0 = tile << 7;

            // wait for batch b's V to be fully scaled
            if (tid == 0) {
                int v;
                do {
                    asm volatile("ld.acquire.gpu.global.s32 %0, [%1];"
                                 : "=r"(v) : "l"(&g_done[b]));
                    if (v < 32) __nanosleep(128);
                } while (v < 32);
            }
            __syncthreads();
            __threadfence();

            {
                int r = tid >> 1, h = tid & 1;
                CP16(smb + OF_KS + r*SKD + h*16,
                     (const char*)(g_k + (size_t)(b*WW + w0 + r)*DD) + h*16);
            }
            {
                int r = tid >> 2, h = tid & 3;
                CP8(smb + OF_QR + r*SKD + h*8,
                    (const char*)(g_q + (size_t)(b*WW + r)*DD) + h*8);
                CP8(smb + OF_QR + 3072 + r*SKD + h*8,
                    (const char*)(g_q + (size_t)(b*WW + 64 + r)*DD) + h*8);
            }
            #pragma unroll
            for (int i = 0; i < 4; i++) {
                int cid = tid + i*256;
                int c = cid >> 3, ch = cid & 7;
                CP16(smb + OF_VS + c*SPJ + ch*16,
                     (const char*)(g_v + (size_t)(b*CC + c)*WW) + ch*16);
            }
            CP_COMMIT(); CP_WAIT0();
            __syncthreads();

            uint32_t ak[4];
            {
                const char* r0 = smc + OF_KS + (wid*16 + g)*SKD + t*4;
                const char* r1 = smc + OF_KS + (wid*16 + g + 8)*SKD + t*4;
                ak[0] = *(const uint32_t*)r0;
                ak[1] = *(const uint32_t*)r1;
                ak[2] = *(const uint32_t*)(r0 + 16);
                ak[3] = *(const uint32_t*)(r1 + 16);
            }

            float acc[16][4];
            #pragma unroll
            for (int ct = 0; ct < 16; ct++)
                #pragma unroll
                for (int e = 0; e < 4; e++) acc[ct][e] = 0.0f;

            for (int jt = 0; jt < 64; jt++) {
                if (jt + 2 < 64) {
                    int r = tid >> 2, h = tid & 3;
                    CP8(smb + OF_QR + ((jt + 2) & 3)*3072 + r*SKD + h*8,
                        (const char*)(g_q + (size_t)(b*WW + (jt + 2)*64 + r)*DD) + h*8);
                }
                if (jt + 1 < 64) {
                    #pragma unroll
                    for (int i = 0; i < 4; i++) {
                        int cid = tid + i*256;
                        int c = cid >> 3, ch = cid & 7;
                        CP16(smb + OF_VS + ((jt + 1) & 1)*18432 + c*SPJ + ch*16,
                             (const char*)(g_v + (size_t)(b*CC + c)*WW + (jt + 1)*64) + ch*16);
                    }
                }
                CP_COMMIT();

                const uint32_t qb = smb + OF_QR + (jt & 3)*3072 + mlane_kd;
                const uint32_t vb = smb + OF_VS + (jt & 1)*18432 + vlane;

                #pragma unroll
                for (int ks = 0; ks < 4; ks++) {
                    uint32_t A[4];
                    {
                        uint32_t q0, q1, q2, q3;
                        LDMX4(q0, q1, q2, q3, qb + (uint32_t)(ks*(16*SKD)));
                        float d[4];
                        mma_z(d, ak, q0, q1);
                        asm("cvt.rn.bf16x2.f32 %0, %1, %2;" : "=r"(A[0]) : "f"(d[1]), "f"(d[0]));
                        asm("cvt.rn.bf16x2.f32 %0, %1, %2;" : "=r"(A[1]) : "f"(d[3]), "f"(d[2]));
                        mma_z(d, ak, q2, q3);
                        asm("cvt.rn.bf16x2.f32 %0, %1, %2;" : "=r"(A[2]) : "f"(d[1]), "f"(d[0]));
                        asm("cvt.rn.bf16x2.f32 %0, %1, %2;" : "=r"(A[3]) : "f"(d[3]), "f"(d[2]));
                        asm("ex2.approx.ftz.bf16x2 %0, %0;" : "+r"(A[0]));
                        asm("ex2.approx.ftz.bf16x2 %0, %0;" : "+r"(A[1]));
                        asm("ex2.approx.ftz.bf16x2 %0, %0;" : "+r"(A[2]));
                        asm("ex2.approx.ftz.bf16x2 %0, %0;" : "+r"(A[3]));
                    }
                    #pragma unroll
                    for (int cp = 0; cp < 8; cp++) {
                        uint32_t v0, v1, v2, v3;
                        uint32_t ad = vb + (uint32_t)(cp*(16*SPJ) + ks*32);
                        LDMX4(v0, v1, v2, v3, ad);
                        mma_acc(acc[2*cp],     A, v0, v1);
                        mma_acc(acc[2*cp + 1], A, v2, v3);
                    }
                }
                CP_WAIT0();
                __syncthreads();
            }

            // ---- epilogue: stage acc -> smem, coalesced out = acc + x ----
            float* es = (float*)smc;
            #pragma unroll
            for (int pp = 0; pp < 2; pp++) {
                __syncthreads();
                #pragma unroll
                for (int ct8 = 0; ct8 < 8; ct8++) {
                    const int ct = pp*8 + ct8;
                    const int cr = ct8*8 + 2*t;
                    const int wl = wid*16 + g;
                    es[(cr    )*132 + wl    ] = acc[ct][0];
                    es[(cr + 1)*132 + wl    ] = acc[ct][1];
                    es[(cr    )*132 + wl + 8] = acc[ct][2];
                    es[(cr + 1)*132 + wl + 8] = acc[ct][3];
                }
                __syncthreads();
                const int c0 = tid >> 3;
                const int l8 = tid & 7;
                #pragma unroll
                for (int cc = 0; cc < 2; cc++) {
                    const int cr = c0 + cc*32;
                    const size_t gbase = (size_t)(b*CC + pp*64 + cr)*WW + w0;
                    #pragma unroll
                    for (int i = 0; i < 4; i++) {
                        const int w = (l8 + i*8)*4;
                        float4 a  = *(float4*)&es[cr*132 + w];
                        float4 xv = *(const float4*)(x + gbase + w);
                        *(float4*)(out + gbase + w) =
                            make_float4(a.x + xv.x, a.y + xv.y, a.z + xv.z, a.w + xv.w);
                    }
                }
            }
            __syncthreads();   // es aliases next item's buffers
        }
    }
}

// ===========================================================================
extern "C" void kernel_launch(void* const* d_in, const int* in_sizes, int n_in,
                              void* d_out, int out_size)
{
    const float* x  = (const float*)d_in[0];
    const float* Wq = (const float*)d_in[1];
    const float* bq = (const float*)d_in[2];
    const float* Wk = (const float*)d_in[3];
    const float* bk = (const float*)d_in[4];
    const float* Wv = (const float*)d_in[5];
    const float* bv = (const float*)d_in[6];
    float* out = (float*)d_out;

    const int smem_proj = 87040;
    const int smem_main = 55296;
    cudaFuncSetAttribute(k_proj, cudaFuncAttributeMaxDynamicSharedMemorySize, smem_proj);
    cudaFuncSetAttribute(k_main, cudaFuncAttributeMaxDynamicSharedMemorySize, smem_main);

    dim3 g(WW/128, BB);
    k_proj<<<g, 256, smem_proj>>>(x, Wq, bq, Wk, bk, Wv, bv);
    k_main<<<296, 256, smem_main>>>(x, out);
}

// round 17
// speedup vs baseline: 1.0763x; 1.0763x over previous
#include <cuda_runtime.h>
#include <cuda_bf16.h>
#include <cstdint>

#define BB 8
#define CC 128
#define WW 4096
#define DD 16

// 0.25 (= D^-0.5) * log2(e): folded into q so softmax uses exp2 directly.
#define QSCALE 0.3606737602222409f

typedef unsigned long long ull;

// ---- scratch (__device__ globals; no allocs allowed) ----------------------
__device__ __nv_bfloat16 g_q[(size_t)BB*WW*DD];   // [b][w][d], pre-scaled
__device__ __nv_bfloat16 g_k[(size_t)BB*WW*DD];   // [b][w][d]
__device__ __nv_bfloat16 g_v[(size_t)BB*CC*WW];   // [b][c][w]; stats scales by 1/l
__device__ __nv_bfloat16 g_wv[CC*CC];             // bf16 Wv (converted once)
__device__ __nv_bfloat16 g_wqk[2*DD*CC];          // bf16 Wq|Wk
__device__ int g_ctr_s, g_ctr_c;                  // work-steal counters

// ---- helpers --------------------------------------------------------------
__device__ __forceinline__ uint32_t smem_u32(const void* p) {
    uint32_t a;
    asm("{ .reg .u64 t; cvta.to.shared.u64 t, %1; cvt.u32.u64 %0, t; }"
        : "=r"(a) : "l"(p));
    return a;
}
__device__ __forceinline__ uint32_t bf2u(__nv_bfloat162 h) {
    return *reinterpret_cast<uint32_t*>(&h);
}

// ---- mma.sync m16n8k16 bf16 (A row-major, B col-major, f32 accum) ---------
__device__ __forceinline__ void mma_acc(float* d, const uint32_t* a,
                                        uint32_t b0, uint32_t b1) {
    asm volatile("mma.sync.aligned.m16n8k16.row.col.f32.bf16.bf16.f32 "
        "{%0,%1,%2,%3}, {%4,%5,%6,%7}, {%8,%9}, {%0,%1,%2,%3};"
        : "+f"(d[0]), "+f"(d[1]), "+f"(d[2]), "+f"(d[3])
        : "r"(a[0]), "r"(a[1]), "r"(a[2]), "r"(a[3]), "r"(b0), "r"(b1));
}
__device__ __forceinline__ void mma_z(float* d, const uint32_t* a,
                                      uint32_t b0, uint32_t b1) {
    asm volatile("mma.sync.aligned.m16n8k16.row.col.f32.bf16.bf16.f32 "
        "{%0,%1,%2,%3}, {%4,%5,%6,%7}, {%8,%9}, {%10,%10,%10,%10};"
        : "=f"(d[0]), "=f"(d[1]), "=f"(d[2]), "=f"(d[3])
        : "r"(a[0]), "r"(a[1]), "r"(a[2]), "r"(a[3]), "r"(b0), "r"(b1),
          "f"(0.0f));
}
#define LDMX4(v0, v1, v2, v3, addr) \
    asm volatile("ldmatrix.sync.aligned.m8n8.x4.shared.b16 {%0,%1,%2,%3}, [%4];" \
        : "=r"(v0), "=r"(v1), "=r"(v2), "=r"(v3) : "r"(addr))

// ---- cp.async -------------------------------------------------------------
#define CP16(dst, src) asm volatile("cp.async.cg.shared.global [%0], [%1], 16;" :: "r"(dst), "l"(src))
#define CP8(dst, src)  asm volatile("cp.async.ca.shared.global [%0], [%1], 8;"  :: "r"(dst), "l"(src))
#define CP_COMMIT()    asm volatile("cp.async.commit_group;" ::: "memory")
#define CP_WAIT0()     asm volatile("cp.async.wait_group 0;" ::: "memory")
#define CP_WAIT1()     asm volatile("cp.async.wait_group 1;" ::: "memory")

// ===========================================================================
// Kernel 0: one-time weight conversion f32 -> bf16; zero counters.
// ===========================================================================
__global__ void __launch_bounds__(256) k_prep(
    const float* __restrict__ Wq, const float* __restrict__ Wk,
    const float* __restrict__ Wv)
{
    const int idx = blockIdx.x*256 + threadIdx.x;   // 80*256 = 20480
    if (idx == 0) { g_ctr_s = 0; g_ctr_c = 0; }
    if (idx < CC*CC) {
        g_wv[idx] = __float2bfloat16(Wv[idx]);
    } else {
        int r = idx - CC*CC;                        // 0..4095
        g_wqk[r] = __float2bfloat16(r < DD*CC ? Wq[r] : Wk[r - DD*CC]);
    }
}

// ===========================================================================
// Kernel 1: projections via bf16 HMMA. Weights now cp.async'd as bf16
// (pre-converted) overlapped with the x transpose.
// ===========================================================================
#define SPX 272
#define OFX 0
#define OFW 34816
#define OFQ 69632
#define OFT 78336

__global__ void __launch_bounds__(256) k_proj(
    const float* __restrict__ x,
    const float* __restrict__ Wq, const float* __restrict__ bq,
    const float* __restrict__ Wk, const float* __restrict__ bk,
    const float* __restrict__ Wv, const float* __restrict__ bv)
{
    extern __shared__ __align__(16) char smc[];
    const uint32_t smb = smem_u32(smc);
    const int b   = blockIdx.y;
    const int w0  = blockIdx.x * 128;
    const int tid = threadIdx.x;
    const int wid = tid >> 5;
    const int lane = tid & 31;
    const int g = lane >> 2, t = lane & 3;

    // weights via cp.async (bf16, 16B chunks), overlapped with x transpose
    #pragma unroll
    for (int i = 0; i < 8; i++) {      // Wv: 128 rows x 16 chunks = 2048
        int cid = tid + i*256;
        int r = cid >> 4, cf = cid & 15;
        CP16(smb + OFW + r*SPX + cf*16, (const char*)g_wv + r*256 + cf*16);
    }
    #pragma unroll
    for (int i = 0; i < 2; i++) {      // Wqk: 32 rows x 16 chunks = 512
        int cid = tid + i*256;
        int r = cid >> 4, cf = cid & 15;
        CP16(smb + OFQ + r*SPX + cf*16, (const char*)g_wqk + r*256 + cf*16);
    }
    CP_COMMIT();

    {   // x -> xT[w][c] bf16 (transpose during store)
        const int c = tid & 127, hf = tid >> 7;
        const float* xp = x + (size_t)(b*CC + c)*WW + w0 + hf*64;
        #pragma unroll
        for (int it = 0; it < 16; it++) {
            float4 v = *(const float4*)(xp + it*4);
            int w = hf*64 + it*4;
            *(__nv_bfloat16*)(smc + OFX + (w  )*SPX + c*2) = __float2bfloat16(v.x);
            *(__nv_bfloat16*)(smc + OFX + (w+1)*SPX + c*2) = __float2bfloat16(v.y);
            *(__nv_bfloat16*)(smc + OFX + (w+2)*SPX + c*2) = __float2bfloat16(v.z);
            *(__nv_bfloat16*)(smc + OFX + (w+3)*SPX + c*2) = __float2bfloat16(v.w);
        }
    }
    CP_WAIT0();
    __syncthreads();

    {   // V GEMM
        const int mb = wid * 16;
        uint32_t A[8][4];
        #pragma unroll
        for (int kt = 0; kt < 8; kt++) {
            const char* r0 = smc + OFW + (mb + g)*SPX + kt*32 + t*4;
            const char* r1 = smc + OFW + (mb + g + 8)*SPX + kt*32 + t*4;
            A[kt][0] = *(const uint32_t*)r0;
            A[kt][1] = *(const uint32_t*)r1;
            A[kt][2] = *(const uint32_t*)(r0 + 16);
            A[kt][3] = *(const uint32_t*)(r1 + 16);
        }
        const float bias0 = bv[mb + g], bias1 = bv[mb + g + 8];
        #pragma unroll
        for (int nt = 0; nt < 16; nt++) {
            float acc[4] = {bias0, bias0, bias1, bias1};
            #pragma unroll
            for (int kt = 0; kt < 8; kt++) {
                const char* bp = smc + OFX + (nt*8 + g)*SPX + kt*32 + t*4;
                uint32_t b0 = *(const uint32_t*)bp;
                uint32_t b1 = *(const uint32_t*)(bp + 16);
                mma_acc(acc, A[kt], b0, b1);
            }
            const int wcol = w0 + nt*8 + 2*t;
            *(uint32_t*)(g_v + (size_t)(b*CC + mb + g)*WW + wcol) =
                bf2u(__floats2bfloat162_rn(acc[0], acc[1]));
            *(uint32_t*)(g_v + (size_t)(b*CC + mb + g + 8)*WW + wcol) =
                bf2u(__floats2bfloat162_rn(acc[2], acc[3]));
        }
    }

    {   // QK GEMM
        const int mt = wid & 1, ntb = (wid >> 1) * 4;
        uint32_t A[8][4];
        #pragma unroll
        for (int kt = 0; kt < 8; kt++) {
            const char* r0 = smc + OFQ + (mt*16 + g)*SPX + kt*32 + t*4;
            const char* r1 = smc + OFQ + (mt*16 + g + 8)*SPX + kt*32 + t*4;
            A[kt][0] = *(const uint32_t*)r0;
            A[kt][1] = *(const uint32_t*)r1;
            A[kt][2] = *(const uint32_t*)(r0 + 16);
            A[kt][3] = *(const uint32_t*)(r1 + 16);
        }
        const float* bias = mt ? bk : bq;
        const float bias0 = bias[g], bias1 = bias[g + 8];
        const float psc = mt ? 1.0f : QSCALE;
        #pragma unroll
        for (int nt = ntb; nt < ntb + 4; nt++) {
            float acc[4] = {bias0, bias0, bias1, bias1};
            #pragma unroll
            for (int kt = 0; kt < 8; kt++) {
                const char* bp = smc + OFX + (nt*8 + g)*SPX + kt*32 + t*4;
                uint32_t b0 = *(const uint32_t*)bp;
                uint32_t b1 = *(const uint32_t*)(bp + 16);
                mma_acc(acc, A[kt], b0, b1);
            }
            const int wcol = nt*8 + 2*t;
            *(uint32_t*)(smc + OFT + (mt*16 + g)*SPX + wcol*2) =
                bf2u(__floats2bfloat162_rn(acc[0]*psc, acc[1]*psc));
            *(uint32_t*)(smc + OFT + (mt*16 + g + 8)*SPX + wcol*2) =
                bf2u(__floats2bfloat162_rn(acc[2]*psc, acc[3]*psc));
        }
    }
    __syncthreads();

    {   // transpose qkT -> g_q/g_k [w][16]
        const int w = tid & 127, half = tid >> 7;
        uint32_t u[8];
        #pragma unroll
        for (int i = 0; i < 8; i++) {
            uint32_t lo = *(const uint16_t*)(smc + OFT + (half*16 + 2*i    )*SPX + w*2);
            uint32_t hi = *(const uint16_t*)(smc + OFT + (half*16 + 2*i + 1)*SPX + w*2);
            u[i] = lo | (hi << 16);
        }
        __nv_bfloat16* op = (half ? g_k : g_q) + (size_t)(b*WW + w0 + w)*DD;
        *(uint4*)op       = make_uint4(u[0], u[1], u[2], u[3]);
        *(uint4*)(op + 8) = make_uint4(u[4], u[5], u[6], u[7]);
    }
}

// ===========================================================================
// Kernel 2: row sums + fold 1/l into V. Warp-autonomous, persistent (R15).
// ===========================================================================
#define SKD 48
__global__ void __launch_bounds__(256, 2) k_stats()
{
    __shared__ __align__(16) char smq[128*SKD];
    __shared__ __align__(16) char smk[8*2*16*SKD];
    __shared__ float partial[8][128];
    __shared__ float red[128];
    __shared__ uint32_t lpk[64];
    __shared__ int s_item;
    const uint32_t QS = smem_u32(smq);
    const uint32_t KB = smem_u32(smk);
    const int tid = threadIdx.x;
    const int wid = tid >> 5;
    const int lane = tid & 31;
    const int g = lane >> 2, t = lane & 3;

    const uint32_t kw = KB + wid*(2*16*SKD);
    const uint32_t kldst = kw + (lane >> 1)*SKD + (lane & 1)*16;
    const uint32_t mlane16 = (uint32_t)((((lane >> 4)*8 + (lane & 7))*SKD)
                                        + ((lane >> 3) & 1)*16);

    while (true) {
        if (tid == 0) s_item = atomicAdd(&g_ctr_s, 1);
        __syncthreads();
        const int item = s_item;
        __syncthreads();
        if (item >= 256) return;
        const int b = item >> 5, j0 = (item & 31) << 7;

        {
            int r = tid >> 1, h = tid & 1;
            CP16(QS + r*SKD + h*16, (const char*)(g_q + (size_t)(b*WW + j0 + r)*DD) + h*16);
            CP16(kldst, (const char*)(g_k + (size_t)(b*WW + wid*16 + (lane >> 1))*DD)
                        + (lane & 1)*16);
        }
        CP_COMMIT(); CP_WAIT0();
        __syncthreads();

        uint32_t A[8][4];
        #pragma unroll
        for (int mt = 0; mt < 8; mt++) {
            const char* r0 = smq + (mt*16 + g)*SKD + t*4;
            const char* r1 = smq + (mt*16 + g + 8)*SKD + t*4;
            A[mt][0] = *(const uint32_t*)r0;
            A[mt][1] = *(const uint32_t*)r1;
            A[mt][2] = *(const uint32_t*)(r0 + 16);
            A[mt][3] = *(const uint32_t*)(r1 + 16);
        }

        float lacc[8][2];
        #pragma unroll
        for (int mt = 0; mt < 8; mt++) { lacc[mt][0] = 0.0f; lacc[mt][1] = 0.0f; }

        for (int it8 = 0; it8 < 4; it8++) {
            uint32_t acc01[8], acc23[8];
            #pragma unroll
            for (int mt = 0; mt < 8; mt++) { acc01[mt] = 0u; acc23[mt] = 0u; }
            #pragma unroll
            for (int i8 = 0; i8 < 8; i8++) {
                const int it = it8*8 + i8;
                if (it + 1 < 32) {
                    CP16(kldst + (uint32_t)(((it + 1) & 1)*(16*SKD)),
                         (const char*)(g_k + (size_t)(b*WW + (it + 1)*128 + wid*16
                                                      + (lane >> 1))*DD) + (lane & 1)*16);
                }
                CP_COMMIT();
                CP_WAIT1();
                uint32_t v0, v1, v2, v3;
                LDMX4(v0, v1, v2, v3, kw + (uint32_t)((it & 1)*(16*SKD)) + mlane16);
                #pragma unroll
                for (int mt = 0; mt < 8; mt++) {
                    float d[4];
                    uint32_t h01, h23;
                    mma_z(d, A[mt], v0, v1);
                    asm("cvt.rn.f16x2.f32 %0, %1, %2;" : "=r"(h01) : "f"(d[1]), "f"(d[0]));
                    asm("cvt.rn.f16x2.f32 %0, %1, %2;" : "=r"(h23) : "f"(d[3]), "f"(d[2]));
                    asm("ex2.approx.f16x2 %0, %0;" : "+r"(h01));
                    asm("ex2.approx.f16x2 %0, %0;" : "+r"(h23));
                    asm("add.rn.f16x2 %0, %0, %1;" : "+r"(acc01[mt]) : "r"(h01));
                    asm("add.rn.f16x2 %0, %0, %1;" : "+r"(acc23[mt]) : "r"(h23));
                    mma_z(d, A[mt], v2, v3);
                    asm("cvt.rn.f16x2.f32 %0, %1, %2;" : "=r"(h01) : "f"(d[1]), "f"(d[0]));
                    asm("cvt.rn.f16x2.f32 %0, %1, %2;" : "=r"(h23) : "f"(d[3]), "f"(d[2]));
                    asm("ex2.approx.f16x2 %0, %0;" : "+r"(h01));
                    asm("ex2.approx.f16x2 %0, %0;" : "+r"(h23));
                    asm("add.rn.f16x2 %0, %0, %1;" : "+r"(acc01[mt]) : "r"(h01));
                    asm("add.rn.f16x2 %0, %0, %1;" : "+r"(acc23[mt]) : "r"(h23));
                }
            }
            #pragma unroll
            for (int mt = 0; mt < 8; mt++) {
                float f0, f1, f2, f3;
                asm("{.reg .f16 lo, hi; mov.b32 {lo, hi}, %2; cvt.f32.f16 %0, lo; cvt.f32.f16 %1, hi;}"
                    : "=f"(f0), "=f"(f1) : "r"(acc01[mt]));
                asm("{.reg .f16 lo, hi; mov.b32 {lo, hi}, %2; cvt.f32.f16 %0, lo; cvt.f32.f16 %1, hi;}"
                    : "=f"(f2), "=f"(f3) : "r"(acc23[mt]));
                lacc[mt][0] += f0 + f1;
                lacc[mt][1] += f2 + f3;
            }
        }

        #pragma unroll
        for (int mt = 0; mt < 8; mt++) {
            #pragma unroll
            for (int off = 1; off < 4; off <<= 1) {
                lacc[mt][0] += __shfl_down_sync(0xffffffffu, lacc[mt][0], off, 4);
                lacc[mt][1] += __shfl_down_sync(0xffffffffu, lacc[mt][1], off, 4);
            }
            if (t == 0) {
                partial[wid][mt*16 + g]     = lacc[mt][0];
                partial[wid][mt*16 + g + 8] = lacc[mt][1];
            }
        }
        __syncthreads();
        if (tid < 128) {
            float l = partial[0][tid] + partial[1][tid] + partial[2][tid] + partial[3][tid]
                    + partial[4][tid] + partial[5][tid] + partial[6][tid] + partial[7][tid];
            red[tid] = 1.0f / l;
        }
        __syncthreads();
        if (tid < 64)
            lpk[tid] = bf2u(__floats2bfloat162_rn(red[2*tid], red[2*tid + 1]));
        __syncthreads();

        {
            const int chunk = tid & 15;
            const int cb    = tid >> 4;
            uint32_t s0 = lpk[chunk*4], s1 = lpk[chunk*4 + 1];
            uint32_t s2 = lpk[chunk*4 + 2], s3 = lpk[chunk*4 + 3];
            #pragma unroll
            for (int c = cb; c < 128; c += 16) {
                uint32_t* vp = (uint32_t*)(g_v + (size_t)(b*CC + c)*WW + j0 + chunk*8);
                uint4 v = *(uint4*)vp;
                asm("mul.rn.bf16x2 %0, %0, %1;" : "+r"(v.x) : "r"(s0));
                asm("mul.rn.bf16x2 %0, %0, %1;" : "+r"(v.y) : "r"(s1));
                asm("mul.rn.bf16x2 %0, %0, %1;" : "+r"(v.z) : "r"(s2));
                asm("mul.rn.bf16x2 %0, %0, %1;" : "+r"(v.w) : "r"(s3));
                *(uint4*)vp = v;
            }
        }
        __syncthreads();
    }
}

// ===========================================================================
// Kernel 3: context + residual. Persistent (R15).
// ===========================================================================
#define SPJ 144
#define OF_KS 0
#define OF_QR 6144
#define OF_VS 18432

__global__ void __launch_bounds__(256, 2) k_ctx(const float* __restrict__ x,
                                                float* __restrict__ out)
{
    extern __shared__ __align__(16) char smc[];
    __shared__ int s_item;
    const uint32_t smb = smem_u32(smc);
    const int tid = threadIdx.x;
    const int wid = tid >> 5;
    const int lane = tid & 31;
    const int g = lane >> 2, t = lane & 3;

    const uint32_t vlane = (uint32_t)((((lane >> 4)*8 + (lane & 7))*SPJ)
                                      + ((lane >> 3) & 1)*16);
    const uint32_t qlane = (uint32_t)((((lane >> 4)*8 + (lane & 7))*SKD)
                                      + ((lane >> 3) & 1)*16);

    while (true) {
        if (tid == 0) s_item = atomicAdd(&g_ctr_c, 1);
        __syncthreads();
        const int item = s_item;
        __syncthreads();
        if (item >= 256) return;
        const int b = item >> 5, w0 = (item & 31) << 7;

        {
            int r = tid >> 1, h = tid & 1;
            CP16(smb + OF_KS + r*SKD + h*16,
                 (const char*)(g_k + (size_t)(b*WW + w0 + r)*DD) + h*16);
        }
        {
            int r = tid >> 2, h = tid & 3;
            CP8(smb + OF_QR + r*SKD + h*8,
                (const char*)(g_q + (size_t)(b*WW + r)*DD) + h*8);
            CP8(smb + OF_QR + 3072 + r*SKD + h*8,
                (const char*)(g_q + (size_t)(b*WW + 64 + r)*DD) + h*8);
        }
        #pragma unroll
        for (int i = 0; i < 4; i++) {
            int cid = tid + i*256;
            int c = cid >> 3, ch = cid & 7;
            CP16(smb + OF_VS + c*SPJ + ch*16,
                 (const char*)(g_v + (size_t)(b*CC + c)*WW) + ch*16);
        }
        CP_COMMIT(); CP_WAIT0();
        __syncthreads();

        uint32_t ak[4];
        {
            const char* r0 = smc + OF_KS + (wid*16 + g)*SKD + t*4;
            const char* r1 = smc + OF_KS + (wid*16 + g + 8)*SKD + t*4;
            ak[0] = *(const uint32_t*)r0;
            ak[1] = *(const uint32_t*)r1;
            ak[2] = *(const uint32_t*)(r0 + 16);
            ak[3] = *(const uint32_t*)(r1 + 16);
        }

        float acc[16][4];
        #pragma unroll
        for (int ct = 0; ct < 16; ct++)
            #pragma unroll
            for (int e = 0; e < 4; e++) acc[ct][e] = 0.0f;

        for (int jt = 0; jt < 64; jt++) {
            if (jt + 2 < 64) {
                int r = tid >> 2, h = tid & 3;
                CP8(smb + OF_QR + ((jt + 2) & 3)*3072 + r*SKD + h*8,
                    (const char*)(g_q + (size_t)(b*WW + (jt + 2)*64 + r)*DD) + h*8);
            }
            if (jt + 1 < 64) {
                #pragma unroll
                for (int i = 0; i < 4; i++) {
                    int cid = tid + i*256;
                    int c = cid >> 3, ch = cid & 7;
                    CP16(smb + OF_VS + ((jt + 1) & 1)*18432 + c*SPJ + ch*16,
                         (const char*)(g_v + (size_t)(b*CC + c)*WW + (jt + 1)*64) + ch*16);
                }
            }
            CP_COMMIT();

            const uint32_t qb = smb + OF_QR + (jt & 3)*3072 + qlane;
            const uint32_t vb = smb + OF_VS + (jt & 1)*18432 + vlane;

            #pragma unroll
            for (int ks = 0; ks < 4; ks++) {
                uint32_t A[4];
                {
                    uint32_t q0, q1, q2, q3;
                    LDMX4(q0, q1, q2, q3, qb + (uint32_t)(ks*(16*SKD)));
                    float d[4];
                    mma_z(d, ak, q0, q1);
                    asm("cvt.rn.bf16x2.f32 %0, %1, %2;" : "=r"(A[0]) : "f"(d[1]), "f"(d[0]));
                    asm("cvt.rn.bf16x2.f32 %0, %1, %2;" : "=r"(A[1]) : "f"(d[3]), "f"(d[2]));
                    mma_z(d, ak, q2, q3);
                    asm("cvt.rn.bf16x2.f32 %0, %1, %2;" : "=r"(A[2]) : "f"(d[1]), "f"(d[0]));
                    asm("cvt.rn.bf16x2.f32 %0, %1, %2;" : "=r"(A[3]) : "f"(d[3]), "f"(d[2]));
                    asm("ex2.approx.ftz.bf16x2 %0, %0;" : "+r"(A[0]));
                    asm("ex2.approx.ftz.bf16x2 %0, %0;" : "+r"(A[1]));
                    asm("ex2.approx.ftz.bf16x2 %0, %0;" : "+r"(A[2]));
                    asm("ex2.approx.ftz.bf16x2 %0, %0;" : "+r"(A[3]));
                }
                #pragma unroll
                for (int cp = 0; cp < 8; cp++) {
                    uint32_t v0, v1, v2, v3;
                    uint32_t ad = vb + (uint32_t)(cp*(16*SPJ) + ks*32);
                    LDMX4(v0, v1, v2, v3, ad);
                    mma_acc(acc[2*cp],     A, v0, v1);
                    mma_acc(acc[2*cp + 1], A, v2, v3);
                }
            }
            CP_WAIT0();
            __syncthreads();
        }

        // ---- epilogue: stage acc -> smem, coalesced out = acc + x ----
        float* es = (float*)smc;
        #pragma unroll
        for (int p = 0; p < 2; p++) {
            __syncthreads();
            #pragma unroll
            for (int ct8 = 0; ct8 < 8; ct8++) {
                const int ct = p*8 + ct8;
                const int cr = ct8*8 + 2*t;
                const int wl = wid*16 + g;
                es[(cr    )*132 + wl    ] = acc[ct][0];
                es[(cr + 1)*132 + wl    ] = acc[ct][1];
                es[(cr    )*132 + wl + 8] = acc[ct][2];
                es[(cr + 1)*132 + wl + 8] = acc[ct][3];
            }
            __syncthreads();
            const int c0 = tid >> 3;
            const int l8 = tid & 7;
            #pragma unroll
            for (int cc = 0; cc < 2; cc++) {
                const int cr = c0 + cc*32;
                const size_t gbase = (size_t)(b*CC + p*64 + cr)*WW + w0;
                #pragma unroll
                for (int i = 0; i < 4; i++) {
                    const int w = (l8 + i*8)*4;
                    float4 a  = *(float4*)&es[cr*132 + w];
                    float4 xv = *(const float4*)(x + gbase + w);
                    *(float4*)(out + gbase + w) =
                        make_float4(a.x + xv.x, a.y + xv.y, a.z + xv.z, a.w + xv.w);
                }
            }
        }
        __syncthreads();
    }
}

// ===========================================================================
extern "C" void kernel_launch(void* const* d_in, const int* in_sizes, int n_in,
                              void* d_out, int out_size)
{
    const float* x  = (const float*)d_in[0];
    const float* Wq = (const float*)d_in[1];
    const float* bq = (const float*)d_in[2];
    const float* Wk = (const float*)d_in[3];
    const float* bk = (const float*)d_in[4];
    const float* Wv = (const float*)d_in[5];
    const float* bv = (const float*)d_in[6];
    float* out = (float*)d_out;

    const int smem_proj = 87040;
    const int smem_ctx  = 55296;
    cudaFuncSetAttribute(k_proj, cudaFuncAttributeMaxDynamicSharedMemorySize, smem_proj);
    cudaFuncSetAttribute(k_ctx,  cudaFuncAttributeMaxDynamicSharedMemorySize, smem_ctx);

    k_prep<<<80, 256>>>(Wq, Wk, Wv);
    dim3 g(WW/128, BB);
    k_proj <<<g, 256, smem_proj>>>(x, Wq, bq, Wk, bk, Wv, bv);
    k_stats<<<296, 256>>>();
    k_ctx  <<<296, 256, smem_ctx>>>(x, out);
}